// round 2
// baseline (speedup 1.0000x reference)
#include <cuda_runtime.h>
#include <cuda_bf16.h>
#include <cstdint>

#define DIMN 640
#define BATCH 64
#define MSP 100
#define TRI 205120           // 640*641/2
#define KPAD 104             // 13 k-steps of 8
#define LDA 108              // smem row stride (conflict-free: 108 mod 32 = 12)
#define SQRT_EPS 0.0031622776601683794f

// -------- scratch (no allocations allowed) --------
__device__ float g_d[BATCH * DIMN];       // squared norms (exact fp32)
__device__ float g_rowsum[BATCH * DIMN];  // full-row sums of dcov
__device__ float g_total[BATCH];          // grand sums

__device__ __forceinline__ unsigned f2tf32(float f) {
    unsigned u;
    asm("cvt.rna.tf32.f32 %0, %1;" : "=r"(u) : "f"(f));
    return u;
}
__device__ __forceinline__ float asqrt(float x) {
    float r;
    asm("sqrt.approx.f32 %0, %1;" : "=f"(r) : "f"(x));
    return r;
}
__device__ __forceinline__ void mma_tf32(float c[4], const unsigned a[4], const unsigned b[2]) {
    asm volatile(
        "mma.sync.aligned.m16n8k8.row.col.f32.tf32.tf32.f32 "
        "{%0,%1,%2,%3}, {%4,%5,%6,%7}, {%8,%9}, {%0,%1,%2,%3};"
        : "+f"(c[0]), "+f"(c[1]), "+f"(c[2]), "+f"(c[3])
        : "r"(a[0]), "r"(a[1]), "r"(a[2]), "r"(a[3]), "r"(b[0]), "r"(b[1]));
}

// ---------------- Kernel 0: exact squared norms + zero rowsums ----------------
__global__ void k_norms(const float* __restrict__ x) {
    int warp = blockIdx.x * 8 + (threadIdx.x >> 5);
    int lane = threadIdx.x & 31;
    if (warp >= BATCH * DIMN) return;
    const float* p = x + (size_t)warp * MSP;
    float s = 0.f;
    for (int m = lane; m < MSP; m += 32) {
        float v = p[m];
        s = fmaf(v, v, s);
    }
    #pragma unroll
    for (int o = 16; o > 0; o >>= 1) s += __shfl_xor_sync(0xffffffffu, s, o);
    if (lane == 0) {
        g_d[warp] = s;
        g_rowsum[warp] = 0.f;
    }
}

// ---------------- Kernel 1: tf32 Gram tiles + fused BDC epilogue ----------------
__global__ void __launch_bounds__(256, 1)
k_bdc(const float* __restrict__ x, const float* __restrict__ tptr, float* __restrict__ out) {
    extern __shared__ float smem[];
    float* As = smem;                 // [128][LDA]
    float* Bs = smem + 128 * LDA;     // [128][LDA]
    __shared__ float rssh[128];
    __shared__ float cssh[128];

    const int tid = threadIdx.x;
    int b = blockIdx.x / 15;
    int p = blockIdx.x % 15;
    int ti = 0;
    while (p >= 5 - ti) { p -= 5 - ti; ti++; }
    int tj = ti + p;

    // load tiles (tf32-converted), K padded with zeros to 104
    const float* xa = x + (size_t)(b * DIMN + ti * 128) * MSP;
    const float* xb = x + (size_t)(b * DIMN + tj * 128) * MSP;
    for (int idx = tid; idx < 128 * MSP; idx += 256) {
        int r = idx / MSP;
        int m = idx - r * MSP;
        As[r * LDA + m] = __uint_as_float(f2tf32(xa[idx]));
        Bs[r * LDA + m] = __uint_as_float(f2tf32(xb[idx]));
    }
    for (int idx = tid; idx < 128 * 4; idx += 256) {
        int r = idx >> 2, c = idx & 3;
        As[r * LDA + MSP + c] = 0.f;
        Bs[r * LDA + MSP + c] = 0.f;
    }
    if (tid < 128) rssh[tid] = 0.f;
    else cssh[tid - 128] = 0.f;
    __syncthreads();

    const int lane = tid & 31;
    const int w = tid >> 5;
    const int wm = (w >> 2) * 64;   // warp m-offset (2 warps in m)
    const int wn = (w & 3) * 32;    // warp n-offset (4 warps in n)
    const int g = lane >> 2;        // 0..7
    const int tg = lane & 3;        // 0..3

    float acc[4][4][4];
    #pragma unroll
    for (int am = 0; am < 4; am++)
        #pragma unroll
        for (int an = 0; an < 4; an++)
            #pragma unroll
            for (int v = 0; v < 4; v++) acc[am][an][v] = 0.f;

    #pragma unroll
    for (int ks = 0; ks < 13; ks++) {
        const int k0 = ks * 8;
        unsigned a[4][4], bf[4][2];
        #pragma unroll
        for (int am = 0; am < 4; am++) {
            const float* r0 = &As[(wm + am * 16 + g) * LDA + k0 + tg];
            const float* r1 = &As[(wm + am * 16 + g + 8) * LDA + k0 + tg];
            a[am][0] = __float_as_uint(r0[0]);
            a[am][1] = __float_as_uint(r1[0]);
            a[am][2] = __float_as_uint(r0[4]);
            a[am][3] = __float_as_uint(r1[4]);
        }
        #pragma unroll
        for (int an = 0; an < 4; an++) {
            const float* br = &Bs[(wn + an * 8 + g) * LDA + k0 + tg];
            bf[an][0] = __float_as_uint(br[0]);
            bf[an][1] = __float_as_uint(br[4]);
        }
        #pragma unroll
        for (int am = 0; am < 4; am++)
            #pragma unroll
            for (int an = 0; an < 4; an++) mma_tf32(acc[am][an], a[am], bf[an]);
    }

    // ---- epilogue ----
    const float s = expf(tptr[0]);
    float drow[8], dcol[8];
    const int rbase = b * DIMN + ti * 128 + wm;
    const int cbase = b * DIMN + tj * 128 + wn;
    #pragma unroll
    for (int am = 0; am < 4; am++) {
        drow[2 * am]     = g_d[rbase + am * 16 + g];
        drow[2 * am + 1] = g_d[rbase + am * 16 + g + 8];
    }
    #pragma unroll
    for (int an = 0; an < 4; an++) {
        dcol[2 * an]     = g_d[cbase + an * 8 + 2 * tg];
        dcol[2 * an + 1] = g_d[cbase + an * 8 + 2 * tg + 1];
    }

    float rp[8], cp[8];
    #pragma unroll
    for (int q = 0; q < 8; q++) { rp[q] = 0.f; cp[q] = 0.f; }

    const int gi0 = ti * 128 + wm;
    const int gj0 = tj * 128 + wn;
    const int ob = b * TRI;

    #pragma unroll
    for (int am = 0; am < 4; am++) {
        #pragma unroll
        for (int an = 0; an < 4; an++) {
            #pragma unroll
            for (int v = 0; v < 4; v++) {
                const int hi = v >> 1, lo = v & 1;
                const int gi = gi0 + am * 16 + g + hi * 8;
                const int gj = gj0 + an * 8 + 2 * tg + lo;
                if (gj >= gi) {  // only upper triangle (always true off-diag tiles)
                    float val;
                    if (gj == gi) {
                        val = SQRT_EPS;
                    } else {
                        float q2 = drow[2 * am + hi] + dcol[2 * an + lo] - 2.f * acc[am][an][v];
                        q2 = fmaxf(q2, 0.f);
                        val = asqrt(fmaf(q2, s, 1e-5f));
                    }
                    out[ob + gi * DIMN - ((gi * (gi - 1)) >> 1) + (gj - gi)] = val;
                    rp[2 * am + hi] += val;
                    if (gj != gi) cp[2 * an + lo] += val;  // diag counted once
                }
            }
        }
    }

    // reduce row partials across the 4 lanes sharing a row (tg dimension)
    #pragma unroll
    for (int q = 0; q < 8; q++) {
        float r = rp[q];
        r += __shfl_xor_sync(0xffffffffu, r, 1);
        r += __shfl_xor_sync(0xffffffffu, r, 2);
        if (tg == 0) atomicAdd(&rssh[wm + (q >> 1) * 16 + g + (q & 1) * 8], r);
    }
    // reduce col partials across the 8 lanes sharing a col (g dimension)
    #pragma unroll
    for (int q = 0; q < 8; q++) {
        float c = cp[q];
        c += __shfl_xor_sync(0xffffffffu, c, 4);
        c += __shfl_xor_sync(0xffffffffu, c, 8);
        c += __shfl_xor_sync(0xffffffffu, c, 16);
        if (g == 0) atomicAdd(&cssh[wn + (q >> 1) * 8 + 2 * tg + (q & 1)], c);
    }
    __syncthreads();
    if (tid < 128) atomicAdd(&g_rowsum[b * DIMN + ti * 128 + tid], rssh[tid]);
    else atomicAdd(&g_rowsum[b * DIMN + tj * 128 + (tid - 128)], cssh[tid - 128]);
}

// ---------------- Kernel 2: per-batch grand totals ----------------
__global__ void k_total() {
    __shared__ float sh[256];
    const int b = blockIdx.x;
    const int tid = threadIdx.x;
    float s = 0.f;
    for (int i = tid; i < DIMN; i += 256) s += g_rowsum[b * DIMN + i];
    sh[tid] = s;
    __syncthreads();
    for (int o = 128; o > 0; o >>= 1) {
        if (tid < o) sh[tid] += sh[tid + o];
        __syncthreads();
    }
    if (tid == 0) g_total[b] = sh[0];
}

// ---------------- Kernel 3: double centering over packed triu ----------------
__global__ void k_center(float* __restrict__ out) {
    const int bid = blockIdx.x;
    const int b = bid / DIMN;
    const int i = bid - b * DIMN;
    const int len = DIMN - i;
    const float inv = 1.f / (float)DIMN;
    const float a = g_total[b] * (1.f / ((float)DIMN * (float)DIMN)) - g_rowsum[b * DIMN + i] * inv;
    float* p = out + (size_t)b * TRI + i * DIMN - ((i * (i - 1)) >> 1);
    const float* rs = &g_rowsum[b * DIMN + i];
    for (int k = threadIdx.x; k < len; k += 128)
        p[k] = p[k] - rs[k] * inv + a;
}

extern "C" void kernel_launch(void* const* d_in, const int* in_sizes, int n_in,
                              void* d_out, int out_size) {
    const float* x = (const float*)d_in[0];
    const float* t = (const float*)d_in[1];
    float* out = (float*)d_out;

    const int smem = 2 * 128 * LDA * (int)sizeof(float);  // 110,592 B
    cudaFuncSetAttribute(k_bdc, cudaFuncAttributeMaxDynamicSharedMemorySize, smem);

    k_norms<<<(BATCH * DIMN) / 8, 256>>>(x);
    k_bdc<<<BATCH * 15, 256, smem>>>(x, t, out);
    k_total<<<BATCH, 256>>>();
    k_center<<<BATCH * DIMN, 128>>>(out);
}